// round 10
// baseline (speedup 1.0000x reference)
#include <cuda_runtime.h>
#include <cuda_bf16.h>
#include <math.h>
#include <stdint.h>

// DelayAndSum: out[b,t] = (1/128) * sum_s x[b, t+d_s, s], zero past T.
// d_s = rint(s*sin(0.5235987755982988)/2) in [0,32].
//
// R10: bulk-copy streaming with 16 KB (32-row) cp.async.bulk chunks.
// 4 warps/CTA x 3-stage x 16KB = 192KB SMEM (1 CTA/SM), 144 CTAs
// (9/batch, 36 warps/batch, 86-87 blocks each). Compute = ring accumulator
// (one LDS.128 + 2 shfl per row; lane m owns output == m mod 32). Warp
// boundaries close via SMEM partial exchange; CTA-edge warp does a guarded
// 32-row global halo. Chunk == output block (32 rows) -> simple epilogue.

#define NTHREADS  128
#define WPB       4
#define CPB       9                   // CTAs per batch
#define WPBATCH   (WPB * CPB)         // 36
#define BPB       3125                // 32-row blocks per batch (T/32)
#define BASE_BLK  (BPB / WPBATCH)     // 86
#define EXTRA     (BPB % WPBATCH)     // 29
#define CHROWS    32
#define CHBYTES   (CHROWS * 512)      // 16384
#define NSTAGE    3

#define SM_STAGES   0
#define SM_SOPEN    (WPB * NSTAGE * CHBYTES)          // 196608
#define SM_MBAR     (SM_SOPEN + WPB * 32 * 4)         // 197120
#define SM_TOTAL    (SM_MBAR + WPB * NSTAGE * 8)      // 197216

__device__ __forceinline__ void mbar_wait(uint32_t mbar, uint32_t phase) {
    asm volatile(
        "{\n\t"
        ".reg .pred P1;\n\t"
        "WAIT_LOOP_%=:\n\t"
        "mbarrier.try_wait.parity.acquire.cta.shared::cta.b64 P1, [%0], %1, 0x989680;\n\t"
        "@P1 bra.uni WAIT_DONE_%=;\n\t"
        "bra.uni WAIT_LOOP_%=;\n\t"
        "WAIT_DONE_%=:\n\t"
        "}"
        :: "r"(mbar), "r"(phase) : "memory");
}

__global__ __launch_bounds__(NTHREADS, 1)
void das7_kernel(const float* __restrict__ x, float* __restrict__ out,
                 int T, uint4 cmask)
{
    extern __shared__ char smem[];
    const uint32_t smem_u32 = (uint32_t)__cvta_generic_to_shared(smem);

    const int w  = threadIdx.x >> 5;
    const int m  = threadIdx.x & 31;
    const int c  = blockIdx.x;
    const int b  = c / CPB;
    const int cb = c % CPB;
    const int wb = cb * WPB + w;

    const int start_blk = wb * BASE_BLK + (wb < EXTRA ? wb : EXTRA);
    const int nblk      = BASE_BLK + (wb < EXTRA ? 1 : 0);   // 86 or 87
    const int t0 = start_blk * 32;
    const int t1 = t0 + nblk * 32;

    const float* __restrict__ xb = x + (size_t)b * (size_t)T * 128;
    float* __restrict__ outb = out + (size_t)b * T;
    float* sopen = (float*)(smem + SM_SOPEN);

    const uint32_t mbar0 = smem_u32 + SM_MBAR + w * (NSTAGE * 8);
    const uint32_t stg0  = smem_u32 + SM_STAGES + w * (NSTAGE * CHBYTES);

    // per-lane split mask: bit j set <=> d(4m+j) == m (row t+m), else d==m+1
    uint32_t mword = (m < 8)  ? cmask.x :
                     (m < 16) ? cmask.y :
                     (m < 24) ? cmask.z : cmask.w;
    uint32_t bits = (mword >> ((m & 7) * 4)) & 0xFu;
    const float f0 = (bits & 1u) ? 1.f : 0.f;
    const float f1 = (bits & 2u) ? 1.f : 0.f;
    const float f2 = (bits & 4u) ? 1.f : 0.f;
    const float f3 = (bits & 8u) ? 1.f : 0.f;
    const float inv = 1.0f / 128.0f;

    // init this warp's mbarriers
    if (m == 0) {
        #pragma unroll
        for (int s = 0; s < NSTAGE; ++s)
            asm volatile("mbarrier.init.shared.b64 [%0], %1;"
                         :: "r"(mbar0 + s * 8), "r"(1) : "memory");
    }
    __syncwarp();

    // prologue: fill the 3-stage pipeline
    if (m == 0) {
        #pragma unroll
        for (int h = 0; h < NSTAGE; ++h) {
            uint32_t bar = mbar0 + h * 8;
            uint32_t dst = stg0 + h * CHBYTES;
            const void* src = (const void*)(xb + (size_t)(t0 + h * CHROWS) * 128);
            asm volatile("mbarrier.arrive.expect_tx.shared.b64 _, [%0], %1;"
                         :: "r"(bar), "r"(CHBYTES) : "memory");
            asm volatile(
                "cp.async.bulk.shared::cluster.global.mbarrier::complete_tx::bytes "
                "[%0], [%1], %2, [%3];"
                :: "r"(dst), "l"(src), "r"(CHBYTES), "r"(bar) : "memory");
        }
    }

    float acc = 0.f, fin = 0.f, open_fin = 0.f;

    #pragma unroll 1
    for (int h = 0; h < nblk; ++h) {
        const int s  = h % NSTAGE;
        const uint32_t ph = (uint32_t)((h / NSTAGE) & 1);
        mbar_wait(mbar0 + s * 8, ph);

        const float4* sb = (const float4*)(smem + w * (NSTAGE * CHBYTES)
                                                + s * CHBYTES) + m;
        #pragma unroll
        for (int k = 0; k < CHROWS; ++k) {
            float4 v = sb[k * 32];
            float tot = (v.x + v.y) + (v.z + v.w);
            float a = fmaf(v.x, f0, fmaf(v.y, f1, fmaf(v.z, f2, v.w * f3)));
            float cc = tot - a;
            int r = (k - m) & 31;
            float u1 = __shfl_sync(0xffffffffu, a, r);
            float u2 = __shfl_sync(0xffffffffu, cc, (r + 31) & 31);
            bool wrap = (r == 0);
            float closed = acc + u2;
            fin = wrap ? closed : fin;
            acc = wrap ? u1 : acc + (u1 + u2);
        }
        __syncwarp();

        // reuse this stage for chunk h+NSTAGE
        if (h + NSTAGE < nblk && m == 0) {
            asm volatile("fence.proxy.async.shared::cta;" ::: "memory");
            uint32_t bar = mbar0 + s * 8;
            uint32_t dst = stg0 + s * CHBYTES;
            const void* src =
                (const void*)(xb + (size_t)(t0 + (h + NSTAGE) * CHROWS) * 128);
            asm volatile("mbarrier.arrive.expect_tx.shared.b64 _, [%0], %1;"
                         :: "r"(bar), "r"(CHBYTES) : "memory");
            asm volatile(
                "cp.async.bulk.shared::cluster.global.mbarrier::complete_tx::bytes "
                "[%0], [%1], %2, [%3];"
                :: "r"(dst), "l"(src), "r"(CHBYTES), "r"(bar) : "memory");
        }

        if (h == 0)
            open_fin = fin;                         // partials for [t0-32, t0)
        else
            outb[t0 + h * 32 - 32 + m] = fin * inv; // outputs closed this chunk
    }
    // acc holds partials for outputs [t1-32, t1) (lane m -> t1-32+m)

    sopen[w * 32 + m] = open_fin;

    if (w == WPB - 1) {
        // CTA-edge warp: close boundary via guarded global halo rows
        const float* xbl = xb + 4 * m;
        #pragma unroll 8
        for (int k = 0; k < 32; ++k) {
            const int t = t1 + k;
            float4 v = make_float4(0.f, 0.f, 0.f, 0.f);
            if (t < T) v = *(const float4*)(xbl + (size_t)t * 128);
            float tot = (v.x + v.y) + (v.z + v.w);
            float a = fmaf(v.x, f0, fmaf(v.y, f1, fmaf(v.z, f2, v.w * f3)));
            float cc = tot - a;
            int r = (k - m) & 31;
            float u1 = __shfl_sync(0xffffffffu, a, r);
            float u2 = __shfl_sync(0xffffffffu, cc, (r + 31) & 31);
            bool wrap = (r == 0);
            float closed = acc + u2;
            fin = wrap ? closed : fin;
            acc = wrap ? u1 : acc + (u1 + u2);
        }
        outb[t1 - 32 + m] = fin * inv;
    }

    __syncthreads();

    if (w < WPB - 1) {
        float final = acc + sopen[(w + 1) * 32 + m];
        outb[t1 - 32 + m] = final * inv;
    }
}

extern "C" void kernel_launch(void* const* d_in, const int* in_sizes, int n_in,
                              void* d_out, int out_size)
{
    const float* x = (const float*)d_in[0];
    float* out = (float*)d_out;

    const int T = 100000;
    const int B = out_size / T;                    // 16

    // Host-side delay split mask (same libm as numpy's round path).
    double q = sin(0.5235987755982988);
    uint32_t cm[4] = {0u, 0u, 0u, 0u};
    for (int l = 0; l < 32; ++l) {
        uint32_t nib = 0u;
        for (int j = 0; j < 4; ++j) {
            int s = 4 * l + j;
            int d = (int)rint((double)s * q / 2.0);
            if (d == l) nib |= (1u << j);
        }
        cm[l >> 3] |= nib << ((l & 7) * 4);
    }
    uint4 cmask = make_uint4(cm[0], cm[1], cm[2], cm[3]);

    static int smem_set = 0;
    if (!smem_set) {
        cudaFuncSetAttribute(das7_kernel,
                             cudaFuncAttributeMaxDynamicSharedMemorySize,
                             SM_TOTAL);
        smem_set = 1;
    }

    const int grid = B * CPB;                      // 144 CTAs
    das7_kernel<<<grid, NTHREADS, SM_TOTAL>>>(x, out, T, cmask);
}

// round 11
// speedup vs baseline: 1.0151x; 1.0151x over previous
#include <cuda_runtime.h>
#include <cuda_bf16.h>
#include <math.h>
#include <stdint.h>

// DelayAndSum: out[b,t] = (1/128) * sum_s x[b, t+d_s, s], zero past T.
// d_s = rint(s*sin(0.5235987755982988)/2) in [0,32].
//
// R11: R9's bulk-copy streaming (8 KB cp.async.bulk chunks, per-warp SMEM
// ring, ring accumulator compute) with NSTAGE=4 and WPB=6:
// 3 chunks (24 KB) in flight per warp x 6 warps = 144 KB/SM (R9: 128 KB).
// 6x4x8KB = 192 KB stages -> 1 CTA/SM, 144 CTAs (9/batch, 54 warps/batch,
// 57-58 blocks each). Warp boundaries close via SMEM partial exchange;
// CTA-edge warp streams a guarded 32-row global halo.

#define NTHREADS  192
#define WPB       6
#define CPB       9                   // CTAs per batch
#define WPBATCH   (WPB * CPB)         // 54
#define BPB       3125                // 32-row blocks per batch (T/32)
#define BASE_BLK  (BPB / WPBATCH)     // 57
#define EXTRA     (BPB % WPBATCH)     // 47
#define CHROWS    16
#define CHBYTES   (CHROWS * 512)      // 8192
#define NSTAGE    4

#define SM_STAGES   0
#define SM_SOPEN    (WPB * NSTAGE * CHBYTES)          // 196608
#define SM_MBAR     (SM_SOPEN + WPB * 32 * 4)         // 197376
#define SM_TOTAL    (SM_MBAR + WPB * NSTAGE * 8)      // 197568

__device__ __forceinline__ void mbar_wait(uint32_t mbar, uint32_t phase) {
    asm volatile(
        "{\n\t"
        ".reg .pred P1;\n\t"
        "WAIT_LOOP_%=:\n\t"
        "mbarrier.try_wait.parity.acquire.cta.shared::cta.b64 P1, [%0], %1, 0x989680;\n\t"
        "@P1 bra.uni WAIT_DONE_%=;\n\t"
        "bra.uni WAIT_LOOP_%=;\n\t"
        "WAIT_DONE_%=:\n\t"
        "}"
        :: "r"(mbar), "r"(phase) : "memory");
}

__global__ __launch_bounds__(NTHREADS, 1)
void das8_kernel(const float* __restrict__ x, float* __restrict__ out,
                 int T, uint4 cmask)
{
    extern __shared__ char smem[];
    const uint32_t smem_u32 = (uint32_t)__cvta_generic_to_shared(smem);

    const int w  = threadIdx.x >> 5;
    const int m  = threadIdx.x & 31;
    const int c  = blockIdx.x;
    const int b  = c / CPB;
    const int cb = c % CPB;
    const int wb = cb * WPB + w;

    const int start_blk = wb * BASE_BLK + (wb < EXTRA ? wb : EXTRA);
    const int nblk      = BASE_BLK + (wb < EXTRA ? 1 : 0);   // 57 or 58
    const int t0  = start_blk * 32;
    const int t1  = t0 + nblk * 32;
    const int nch = nblk * 2;                     // 16-row chunks

    const float* __restrict__ xb = x + (size_t)b * (size_t)T * 128;
    float* __restrict__ outb = out + (size_t)b * T;
    float* sopen = (float*)(smem + SM_SOPEN);

    const uint32_t mbar0 = smem_u32 + SM_MBAR + w * (NSTAGE * 8);
    const uint32_t stg0  = smem_u32 + SM_STAGES + w * (NSTAGE * CHBYTES);

    // per-lane split mask: bit j set <=> d(4m+j) == m (row t+m), else d==m+1
    uint32_t mword = (m < 8)  ? cmask.x :
                     (m < 16) ? cmask.y :
                     (m < 24) ? cmask.z : cmask.w;
    uint32_t bits = (mword >> ((m & 7) * 4)) & 0xFu;
    const float f0 = (bits & 1u) ? 1.f : 0.f;
    const float f1 = (bits & 2u) ? 1.f : 0.f;
    const float f2 = (bits & 4u) ? 1.f : 0.f;
    const float f3 = (bits & 8u) ? 1.f : 0.f;
    const float inv = 1.0f / 128.0f;

    // init this warp's mbarriers
    if (m == 0) {
        #pragma unroll
        for (int s = 0; s < NSTAGE; ++s)
            asm volatile("mbarrier.init.shared.b64 [%0], %1;"
                         :: "r"(mbar0 + s * 8), "r"(1) : "memory");
    }
    __syncwarp();

    // prologue: fill the 4-stage pipeline
    if (m == 0) {
        #pragma unroll
        for (int h = 0; h < NSTAGE; ++h) {
            uint32_t bar = mbar0 + h * 8;
            uint32_t dst = stg0 + h * CHBYTES;
            const void* src = (const void*)(xb + (size_t)(t0 + h * CHROWS) * 128);
            asm volatile("mbarrier.arrive.expect_tx.shared.b64 _, [%0], %1;"
                         :: "r"(bar), "r"(CHBYTES) : "memory");
            asm volatile(
                "cp.async.bulk.shared::cluster.global.mbarrier::complete_tx::bytes "
                "[%0], [%1], %2, [%3];"
                :: "r"(dst), "l"(src), "r"(CHBYTES), "r"(bar) : "memory");
        }
    }

    float acc = 0.f, fin = 0.f, open_fin = 0.f;

    #pragma unroll 1
    for (int h = 0; h < nch; ++h) {
        const int s  = h & (NSTAGE - 1);
        const uint32_t ph = (uint32_t)((h >> 2) & 1);
        mbar_wait(mbar0 + s * 8, ph);

        const float4* sb = (const float4*)(smem + w * (NSTAGE * CHBYTES)
                                                + s * CHBYTES) + m;
        const int kbase = (h & 1) << 4;
        #pragma unroll
        for (int i = 0; i < CHROWS; ++i) {
            float4 v = sb[i * 32];
            float tot = (v.x + v.y) + (v.z + v.w);
            float a = fmaf(v.x, f0, fmaf(v.y, f1, fmaf(v.z, f2, v.w * f3)));
            float cc = tot - a;
            int k = kbase + i;
            int r = (k - m) & 31;
            float u1 = __shfl_sync(0xffffffffu, a, r);
            float u2 = __shfl_sync(0xffffffffu, cc, (r + 31) & 31);
            bool wrap = (r == 0);
            float closed = acc + u2;
            fin = wrap ? closed : fin;
            acc = wrap ? u1 : acc + (u1 + u2);
        }
        __syncwarp();

        // reuse this stage for chunk h+NSTAGE
        if (h + NSTAGE < nch && m == 0) {
            asm volatile("fence.proxy.async.shared::cta;" ::: "memory");
            uint32_t bar = mbar0 + s * 8;
            uint32_t dst = stg0 + s * CHBYTES;
            const void* src =
                (const void*)(xb + (size_t)(t0 + (h + NSTAGE) * CHROWS) * 128);
            asm volatile("mbarrier.arrive.expect_tx.shared.b64 _, [%0], %1;"
                         :: "r"(bar), "r"(CHBYTES) : "memory");
            asm volatile(
                "cp.async.bulk.shared::cluster.global.mbarrier::complete_tx::bytes "
                "[%0], [%1], %2, [%3];"
                :: "r"(dst), "l"(src), "r"(CHBYTES), "r"(bar) : "memory");
        }

        if (h & 1) {
            const int lb = h >> 1;
            if (lb == 0)
                open_fin = fin;      // partials for outputs [t0-32, t0)
            else
                outb[t0 + lb * 32 - 32 + m] = fin * inv;
        }
    }
    // acc holds partials for outputs [t1-32, t1) (lane m -> t1-32+m)

    sopen[w * 32 + m] = open_fin;

    if (w == WPB - 1) {
        // CTA-edge warp: close boundary via guarded global halo rows
        const float* xbl = xb + 4 * m;
        #pragma unroll 8
        for (int k = 0; k < 32; ++k) {
            const int t = t1 + k;
            float4 v = make_float4(0.f, 0.f, 0.f, 0.f);
            if (t < T) v = *(const float4*)(xbl + (size_t)t * 128);
            float tot = (v.x + v.y) + (v.z + v.w);
            float a = fmaf(v.x, f0, fmaf(v.y, f1, fmaf(v.z, f2, v.w * f3)));
            float cc = tot - a;
            int r = (k - m) & 31;
            float u1 = __shfl_sync(0xffffffffu, a, r);
            float u2 = __shfl_sync(0xffffffffu, cc, (r + 31) & 31);
            bool wrap = (r == 0);
            float closed = acc + u2;
            fin = wrap ? closed : fin;
            acc = wrap ? u1 : acc + (u1 + u2);
        }
        outb[t1 - 32 + m] = fin * inv;
    }

    __syncthreads();

    if (w < WPB - 1) {
        float final = acc + sopen[(w + 1) * 32 + m];
        outb[t1 - 32 + m] = final * inv;
    }
}

extern "C" void kernel_launch(void* const* d_in, const int* in_sizes, int n_in,
                              void* d_out, int out_size)
{
    const float* x = (const float*)d_in[0];
    float* out = (float*)d_out;

    const int T = 100000;
    const int B = out_size / T;                    // 16

    // Host-side delay split mask (same libm as numpy's round path).
    double q = sin(0.5235987755982988);
    uint32_t cm[4] = {0u, 0u, 0u, 0u};
    for (int l = 0; l < 32; ++l) {
        uint32_t nib = 0u;
        for (int j = 0; j < 4; ++j) {
            int s = 4 * l + j;
            int d = (int)rint((double)s * q / 2.0);
            if (d == l) nib |= (1u << j);
        }
        cm[l >> 3] |= nib << ((l & 7) * 4);
    }
    uint4 cmask = make_uint4(cm[0], cm[1], cm[2], cm[3]);

    static int smem_set = 0;
    if (!smem_set) {
        cudaFuncSetAttribute(das8_kernel,
                             cudaFuncAttributeMaxDynamicSharedMemorySize,
                             SM_TOTAL);
        smem_set = 1;
    }

    const int grid = B * CPB;                      // 144 CTAs
    das8_kernel<<<grid, NTHREADS, SM_TOTAL>>>(x, out, T, cmask);
}

// round 12
// speedup vs baseline: 1.0325x; 1.0171x over previous
#include <cuda_runtime.h>
#include <cuda_bf16.h>
#include <math.h>
#include <stdint.h>

// DelayAndSum: out[b,t] = (1/128) * sum_s x[b, t+d_s, s], zero past T.
// d_s = rint(s*sin(0.5235987755982988)/2) in [0,32].
//
// R12 = R9 (winning shape: 8 warps/CTA, 3-stage x 8 KB cp.async.bulk ring
// per warp, ring-accumulator compute) with the grid decoupled from batches:
// 152 CTAs (one per GB300 SM; R9 idled 8 SMs) x 8 warps = 1216 warps =
// 76 warps per batch, each owning 41-42 contiguous 32-row blocks.
// Boundary closure: intra-CTA same-batch -> SMEM partial exchange;
// CTA edge (w==7) or batch edge (r==75) -> guarded 32-row global halo.

#define NTHREADS  256
#define WPB       8
#define NCTAS     152
#define WTOT      (NCTAS * WPB)       // 1216
#define NBATCH    16
#define WPBATCH   (WTOT / NBATCH)     // 76
#define BPB       3125                // 32-row blocks per batch (T/32)
#define BASE_BLK  (BPB / WPBATCH)     // 41
#define EXTRA     (BPB % WPBATCH)     // 9
#define CHROWS    16
#define CHBYTES   (CHROWS * 512)      // 8192
#define NSTAGE    3

#define SM_STAGES   0
#define SM_SOPEN    (WPB * NSTAGE * CHBYTES)          // 196608
#define SM_MBAR     (SM_SOPEN + WPB * 32 * 4)         // 197632
#define SM_TOTAL    (SM_MBAR + WPB * NSTAGE * 8)      // 197824

__device__ __forceinline__ void mbar_wait(uint32_t mbar, uint32_t phase) {
    asm volatile(
        "{\n\t"
        ".reg .pred P1;\n\t"
        "WAIT_LOOP_%=:\n\t"
        "mbarrier.try_wait.parity.acquire.cta.shared::cta.b64 P1, [%0], %1, 0x989680;\n\t"
        "@P1 bra.uni WAIT_DONE_%=;\n\t"
        "bra.uni WAIT_LOOP_%=;\n\t"
        "WAIT_DONE_%=:\n\t"
        "}"
        :: "r"(mbar), "r"(phase) : "memory");
}

__global__ __launch_bounds__(NTHREADS, 1)
void das9_kernel(const float* __restrict__ x, float* __restrict__ out,
                 int T, uint4 cmask)
{
    extern __shared__ char smem[];
    const uint32_t smem_u32 = (uint32_t)__cvta_generic_to_shared(smem);

    const int w  = threadIdx.x >> 5;
    const int m  = threadIdx.x & 31;
    const int g  = blockIdx.x * WPB + w;           // global warp id
    const int b  = g / WPBATCH;                    // batch
    const int r  = g % WPBATCH;                    // warp rank within batch

    const int start_blk = r * BASE_BLK + (r < EXTRA ? r : EXTRA);
    const int nblk      = BASE_BLK + (r < EXTRA ? 1 : 0);   // 41 or 42
    const int t0  = start_blk * 32;
    const int t1  = t0 + nblk * 32;
    const int nch = nblk * 2;                      // 16-row chunks

    // halo closure needed at CTA edges and batch edges
    const bool haloClose = (w == WPB - 1) || (r == WPBATCH - 1);

    const float* __restrict__ xb = x + (size_t)b * (size_t)T * 128;
    float* __restrict__ outb = out + (size_t)b * T;
    float* sopen = (float*)(smem + SM_SOPEN);

    const uint32_t mbar0 = smem_u32 + SM_MBAR + w * (NSTAGE * 8);
    const uint32_t stg0  = smem_u32 + SM_STAGES + w * (NSTAGE * CHBYTES);

    // per-lane split mask: bit j set <=> d(4m+j) == m (row t+m), else d==m+1
    uint32_t mword = (m < 8)  ? cmask.x :
                     (m < 16) ? cmask.y :
                     (m < 24) ? cmask.z : cmask.w;
    uint32_t bits = (mword >> ((m & 7) * 4)) & 0xFu;
    const float f0 = (bits & 1u) ? 1.f : 0.f;
    const float f1 = (bits & 2u) ? 1.f : 0.f;
    const float f2 = (bits & 4u) ? 1.f : 0.f;
    const float f3 = (bits & 8u) ? 1.f : 0.f;
    const float inv = 1.0f / 128.0f;

    // init this warp's mbarriers
    if (m == 0) {
        #pragma unroll
        for (int s = 0; s < NSTAGE; ++s)
            asm volatile("mbarrier.init.shared.b64 [%0], %1;"
                         :: "r"(mbar0 + s * 8), "r"(1) : "memory");
    }
    __syncwarp();

    // prologue: fill the 3-stage pipeline
    if (m == 0) {
        #pragma unroll
        for (int h = 0; h < NSTAGE; ++h) {
            uint32_t bar = mbar0 + h * 8;
            uint32_t dst = stg0 + h * CHBYTES;
            const void* src = (const void*)(xb + (size_t)(t0 + h * CHROWS) * 128);
            asm volatile("mbarrier.arrive.expect_tx.shared.b64 _, [%0], %1;"
                         :: "r"(bar), "r"(CHBYTES) : "memory");
            asm volatile(
                "cp.async.bulk.shared::cluster.global.mbarrier::complete_tx::bytes "
                "[%0], [%1], %2, [%3];"
                :: "r"(dst), "l"(src), "r"(CHBYTES), "r"(bar) : "memory");
        }
    }

    float acc = 0.f, fin = 0.f, open_fin = 0.f;

    #pragma unroll 1
    for (int h = 0; h < nch; ++h) {
        const int s  = h % NSTAGE;
        const uint32_t ph = (uint32_t)((h / NSTAGE) & 1);
        mbar_wait(mbar0 + s * 8, ph);

        const float4* sb = (const float4*)(smem + w * (NSTAGE * CHBYTES)
                                                + s * CHBYTES) + m;
        const int kbase = (h & 1) << 4;
        #pragma unroll
        for (int i = 0; i < CHROWS; ++i) {
            float4 v = sb[i * 32];
            float tot = (v.x + v.y) + (v.z + v.w);
            float a = fmaf(v.x, f0, fmaf(v.y, f1, fmaf(v.z, f2, v.w * f3)));
            float cc = tot - a;
            int k = kbase + i;
            int rr = (k - m) & 31;
            float u1 = __shfl_sync(0xffffffffu, a, rr);
            float u2 = __shfl_sync(0xffffffffu, cc, (rr + 31) & 31);
            bool wrap = (rr == 0);
            float closed = acc + u2;
            fin = wrap ? closed : fin;
            acc = wrap ? u1 : acc + (u1 + u2);
        }
        __syncwarp();

        // reuse this stage for chunk h+NSTAGE
        if (h + NSTAGE < nch && m == 0) {
            asm volatile("fence.proxy.async.shared::cta;" ::: "memory");
            uint32_t bar = mbar0 + s * 8;
            uint32_t dst = stg0 + s * CHBYTES;
            const void* src =
                (const void*)(xb + (size_t)(t0 + (h + NSTAGE) * CHROWS) * 128);
            asm volatile("mbarrier.arrive.expect_tx.shared.b64 _, [%0], %1;"
                         :: "r"(bar), "r"(CHBYTES) : "memory");
            asm volatile(
                "cp.async.bulk.shared::cluster.global.mbarrier::complete_tx::bytes "
                "[%0], [%1], %2, [%3];"
                :: "r"(dst), "l"(src), "r"(CHBYTES), "r"(bar) : "memory");
        }

        if (h & 1) {
            const int lb = h >> 1;
            if (lb == 0)
                open_fin = fin;      // partials for outputs [t0-32, t0)
            else
                outb[t0 + lb * 32 - 32 + m] = fin * inv;
        }
    }
    // acc holds partials for outputs [t1-32, t1) (lane m -> t1-32+m)

    sopen[w * 32 + m] = open_fin;

    if (haloClose) {
        // close boundary via guarded global halo rows (zero-pad past T)
        const float* xbl = xb + 4 * m;
        #pragma unroll 8
        for (int k = 0; k < 32; ++k) {
            const int t = t1 + k;
            float4 v = make_float4(0.f, 0.f, 0.f, 0.f);
            if (t < T) v = *(const float4*)(xbl + (size_t)t * 128);
            float tot = (v.x + v.y) + (v.z + v.w);
            float a = fmaf(v.x, f0, fmaf(v.y, f1, fmaf(v.z, f2, v.w * f3)));
            float cc = tot - a;
            int rr = (k - m) & 31;
            float u1 = __shfl_sync(0xffffffffu, a, rr);
            float u2 = __shfl_sync(0xffffffffu, cc, (rr + 31) & 31);
            bool wrap = (rr == 0);
            float closed = acc + u2;
            fin = wrap ? closed : fin;
            acc = wrap ? u1 : acc + (u1 + u2);
        }
        outb[t1 - 32 + m] = fin * inv;
    }

    __syncthreads();

    if (!haloClose) {
        // next warp (same CTA, same batch) supplies complementary partials
        float final = acc + sopen[(w + 1) * 32 + m];
        outb[t1 - 32 + m] = final * inv;
    }
}

extern "C" void kernel_launch(void* const* d_in, const int* in_sizes, int n_in,
                              void* d_out, int out_size)
{
    const float* x = (const float*)d_in[0];
    float* out = (float*)d_out;

    const int T = 100000;

    // Host-side delay split mask (same libm as numpy's round path).
    double q = sin(0.5235987755982988);
    uint32_t cm[4] = {0u, 0u, 0u, 0u};
    for (int l = 0; l < 32; ++l) {
        uint32_t nib = 0u;
        for (int j = 0; j < 4; ++j) {
            int s = 4 * l + j;
            int d = (int)rint((double)s * q / 2.0);
            if (d == l) nib |= (1u << j);
        }
        cm[l >> 3] |= nib << ((l & 7) * 4);
    }
    uint4 cmask = make_uint4(cm[0], cm[1], cm[2], cm[3]);

    static int smem_set = 0;
    if (!smem_set) {
        cudaFuncSetAttribute(das9_kernel,
                             cudaFuncAttributeMaxDynamicSharedMemorySize,
                             SM_TOTAL);
        smem_set = 1;
    }

    das9_kernel<<<NCTAS, NTHREADS, SM_TOTAL>>>(x, out, T, cmask);
}